// round 8
// baseline (speedup 1.0000x reference)
#include <cuda_runtime.h>

#define H 16
#define T 2048
#define D 1024
#define DH 64
#define N3 3072
#define PI 128

// ---------------- scratch (no allocations allowed) ----------------
__device__ float g_q[H*T*DH];
__device__ float g_k[H*T*DH];
__device__ float g_v[H*T*DH];
__device__ float g_ao[H*T*DH];
__device__ int   g_cum[T];
__device__ float g_ns[8][H*DH*DH];   // newstate partials per chunk-group

// ---------------- packed f32x2 helpers ----------------
__device__ __forceinline__ void ffma2(unsigned long long& d, unsigned long long a, unsigned long long b) {
    asm("fma.rn.f32x2 %0, %1, %2, %0;" : "+l"(d) : "l"(a), "l"(b));
}
__device__ __forceinline__ void upk(unsigned long long v, float& lo, float& hi) {
    asm("mov.b64 {%0,%1}, %2;" : "=f"(lo), "=f"(hi) : "l"(v));
}

// ---------------- cumsum of done (dtype auto-detect) ----------------
__global__ void cumsum_kernel(const unsigned char* __restrict__ done) {
    __shared__ int tsum[256];
    __shared__ int s_big, s_off4;
    int tid = threadIdx.x;
    if (tid == 0) { s_big = 0; s_off4 = 0; }
    __syncthreads();
    int big = 0, off4 = 0;
    for (int i = tid; i < 2048; i += 256) {
        unsigned char bb = done[i];
        if (bb > 1) big = 1;
        if (bb != 0 && (i & 3) != 0) off4 = 1;
    }
    if (big)  atomicOr(&s_big, 1);
    if (off4) atomicOr(&s_off4, 1);
    __syncthreads();
    int mode = s_big ? 2 : (s_off4 ? 0 : 1);  // 0=bool, 1=int32, 2=float32

    int loc[8]; int s = 0;
#pragma unroll
    for (int i = 0; i < 8; i++) {
        int t = tid*8 + i;
        int v;
        if (mode == 0)      v = (done[t] != 0);
        else if (mode == 1) v = (((const int*)done)[t] != 0);
        else                v = (((const float*)done)[t] != 0.0f);
        loc[i] = v; s += v;
    }
    tsum[tid] = s; __syncthreads();
    for (int off = 1; off < 256; off <<= 1) {
        int v = (tid >= off) ? tsum[tid - off] : 0;
        __syncthreads();
        tsum[tid] += v;
        __syncthreads();
    }
    int run = (tid > 0) ? tsum[tid-1] : 0;
#pragma unroll
    for (int i = 0; i < 8; i++) { run += loc[i]; g_cum[tid*8 + i] = run; }
}

// ---------------- FFMA2 GEMM core ----------------
// Block tile 128(M) x 64(N), K panel 16, 256 threads, thread tile 8x4.
// As: [k][m] transposed (m-pairs contiguous). Bs: duplicated (each n stored twice).
// acc packed along M: acc[mp][j] holds rows (ty*8+2mp, ty*8+2mp+1), col tx*4+j.

// qkv: x(2048x1024) @ w_qkv(1024x3072) + b, scatter to g_q/g_k/g_v (H,T,DH)
__global__ void qkv_gemm_kernel(const float* __restrict__ x,
                                const float* __restrict__ w,
                                const float* __restrict__ b) {
    __shared__ float As[16][128];
    __shared__ float Bs[16][128];
    int bm = blockIdx.y, bn = blockIdx.x;
    int tid = threadIdx.x;
    int tx = tid & 15, ty = tid >> 4;

    unsigned long long acc[4][4] = {};

    int arow = tid >> 1, akk = (tid & 1) * 8;
    int bkk = tid >> 4, bn4 = (tid & 15) * 4;
    const float* xp = x + (bm*128 + arow)*D + akk;
    const float* wp = w + bkk*N3 + bn*64 + bn4;

    for (int kt = 0; kt < D/16; kt++) {
        float4 a0 = *(const float4*)(xp + kt*16);
        float4 a1 = *(const float4*)(xp + kt*16 + 4);
        As[akk+0][arow] = a0.x; As[akk+1][arow] = a0.y;
        As[akk+2][arow] = a0.z; As[akk+3][arow] = a0.w;
        As[akk+4][arow] = a1.x; As[akk+5][arow] = a1.y;
        As[akk+6][arow] = a1.z; As[akk+7][arow] = a1.w;
        float4 bv = *(const float4*)(wp + kt*16*N3);
        *(float2*)&Bs[bkk][(bn4+0)*2] = make_float2(bv.x, bv.x);
        *(float2*)&Bs[bkk][(bn4+1)*2] = make_float2(bv.y, bv.y);
        *(float2*)&Bs[bkk][(bn4+2)*2] = make_float2(bv.z, bv.z);
        *(float2*)&Bs[bkk][(bn4+3)*2] = make_float2(bv.w, bv.w);
        __syncthreads();
#pragma unroll
        for (int kk = 0; kk < 16; kk++) {
            ulonglong2 aq0 = *(const ulonglong2*)&As[kk][ty*8];
            ulonglong2 aq1 = *(const ulonglong2*)&As[kk][ty*8 + 4];
            ulonglong2 bq0 = *(const ulonglong2*)&Bs[kk][tx*8];
            ulonglong2 bq1 = *(const ulonglong2*)&Bs[kk][tx*8 + 4];
            unsigned long long aa[4] = {aq0.x, aq0.y, aq1.x, aq1.y};
            unsigned long long bb[4] = {bq0.x, bq0.y, bq1.x, bq1.y};
#pragma unroll
            for (int mp = 0; mp < 4; mp++)
#pragma unroll
                for (int j = 0; j < 4; j++) ffma2(acc[mp][j], aa[mp], bb[j]);
        }
        __syncthreads();
    }
#pragma unroll
    for (int mp = 0; mp < 4; mp++) {
        int m0 = bm*128 + ty*8 + mp*2;
#pragma unroll
        for (int j = 0; j < 4; j++) {
            int n = bn*64 + tx*4 + j;
            float lo, hi; upk(acc[mp][j], lo, hi);
            float bias = b[n];
            int qkv = n >> 10;
            int h   = (n >> 6) & 15;
            int dh  = n & 63;
            float* dst = (qkv == 0) ? g_q : ((qkv == 1) ? g_k : g_v);
            dst[(h*T + m0    )*DH + dh] = lo + bias;
            dst[(h*T + m0 + 1)*DH + dh] = hi + bias;
        }
    }
}

// out projection: ao(T x D, head-chunked layout) @ w_out(1024x1024) + b_out
__global__ void out_gemm_kernel(const float* __restrict__ w,
                                const float* __restrict__ b,
                                float* __restrict__ xout) {
    __shared__ float As[16][128];
    __shared__ float Bs[16][128];
    int bm = blockIdx.y, bn = blockIdx.x;
    int tid = threadIdx.x;
    int tx = tid & 15, ty = tid >> 4;

    unsigned long long acc[4][4] = {};

    int arow = tid >> 1, akk = (tid & 1) * 8;
    int bkk = tid >> 4, bn4 = (tid & 15) * 4;
    int m = bm*128 + arow;

    for (int kt = 0; kt < D/16; kt++) {
        int k  = kt*16 + akk;
        int hh = k >> 6, dh = k & 63;   // 8 consecutive k stay within one head chunk
        const float* ap = g_ao + (hh*T + m)*DH + dh;
        float4 a0 = *(const float4*)(ap);
        float4 a1 = *(const float4*)(ap + 4);
        As[akk+0][arow] = a0.x; As[akk+1][arow] = a0.y;
        As[akk+2][arow] = a0.z; As[akk+3][arow] = a0.w;
        As[akk+4][arow] = a1.x; As[akk+5][arow] = a1.y;
        As[akk+6][arow] = a1.z; As[akk+7][arow] = a1.w;
        float4 bv = *(const float4*)(w + (kt*16 + bkk)*D + bn*64 + bn4);
        *(float2*)&Bs[bkk][(bn4+0)*2] = make_float2(bv.x, bv.x);
        *(float2*)&Bs[bkk][(bn4+1)*2] = make_float2(bv.y, bv.y);
        *(float2*)&Bs[bkk][(bn4+2)*2] = make_float2(bv.z, bv.z);
        *(float2*)&Bs[bkk][(bn4+3)*2] = make_float2(bv.w, bv.w);
        __syncthreads();
#pragma unroll
        for (int kk = 0; kk < 16; kk++) {
            ulonglong2 aq0 = *(const ulonglong2*)&As[kk][ty*8];
            ulonglong2 aq1 = *(const ulonglong2*)&As[kk][ty*8 + 4];
            ulonglong2 bq0 = *(const ulonglong2*)&Bs[kk][tx*8];
            ulonglong2 bq1 = *(const ulonglong2*)&Bs[kk][tx*8 + 4];
            unsigned long long aa[4] = {aq0.x, aq0.y, aq1.x, aq1.y};
            unsigned long long bb[4] = {bq0.x, bq0.y, bq1.x, bq1.y};
#pragma unroll
            for (int mp = 0; mp < 4; mp++)
#pragma unroll
                for (int j = 0; j < 4; j++) ffma2(acc[mp][j], aa[mp], bb[j]);
        }
        __syncthreads();
    }
#pragma unroll
    for (int mp = 0; mp < 4; mp++) {
        int m0 = bm*128 + ty*8 + mp*2;
#pragma unroll
        for (int j = 0; j < 4; j++) {
            int n = bn*64 + tx*4 + j;
            float lo, hi; upk(acc[mp][j], lo, hi);
            float bias = b[n];
            xout[(m0    )*D + n] = lo + bias;
            xout[(m0 + 1)*D + n] = hi + bias;
        }
    }
}

// ---------------- attention (unchanged, known-good) ----------------
__global__ void attn_kernel(const float* __restrict__ state) {
    extern __shared__ float sm[];
    float* qs = sm;                   // [64][PI]  q transposed: qs[d][i]
    float* ks = qs + 64*PI;           // [64][68]  k transposed: ks[d][j] (also state)
    float* vs = ks + 64*68;           // [64][64]  vs[j][d]
    float* Ss = vs + 64*64;           // [64][PI]  S transposed: Ss[j][i]
    int*   cq = (int*)(Ss + 64*PI);   // [128]
    int*   ck = cq + 128;             // [64]

    int h  = blockIdx.y;
    int tb = blockIdx.x;
    int t0 = tb * 128;
    int tid = threadIdx.x;
    int tx = tid & 15, ty = tid >> 4;

    const float* qg = g_q + (h*T + t0)*DH;
#pragma unroll
    for (int r = 0; r < 8; r++) {
        int idx = tid + r*256;
        int i = idx >> 4, c4 = (idx & 15) * 4;
        float4 a = *(const float4*)(qg + i*DH + c4);
        qs[(c4+0)*PI + i] = a.x;
        qs[(c4+1)*PI + i] = a.y;
        qs[(c4+2)*PI + i] = a.z;
        qs[(c4+3)*PI + i] = a.w;
    }
    if (tid < 128) cq[tid] = g_cum[t0 + tid];
    __syncthreads();

    float acc[8][4] = {};
    int cum_t0 = cq[0];

    int sb_max = 2*tb + 1;
    for (int sb = 0; sb <= sb_max; sb++) {
        int s0 = sb * 64;
        if (g_cum[s0 + 63] < cum_t0) continue;

        const float* kg = g_k + (h*T + s0)*DH;
        const float* vg = g_v + (h*T + s0)*DH;
#pragma unroll
        for (int r = 0; r < 4; r++) {
            int idx = tid + r*256;
            int j = idx >> 4, c4 = (idx & 15) * 4;
            float4 a = *(const float4*)(kg + j*DH + c4);
            ks[(c4+0)*68 + j] = a.x;
            ks[(c4+1)*68 + j] = a.y;
            ks[(c4+2)*68 + j] = a.z;
            ks[(c4+3)*68 + j] = a.w;
            *(float4*)&vs[j*64 + c4] = *(const float4*)(vg + j*DH + c4);
        }
        if (tid < 64) ck[tid] = g_cum[s0 + tid];
        __syncthreads();

        float sacc[8][4] = {};
#pragma unroll 8
        for (int d = 0; d < 64; d++) {
            float4 a0 = *(const float4*)&qs[d*PI + ty*8];
            float4 a1 = *(const float4*)&qs[d*PI + ty*8 + 4];
            float4 bv = *(const float4*)&ks[d*68 + tx*4];
            float aa[8] = {a0.x,a0.y,a0.z,a0.w,a1.x,a1.y,a1.z,a1.w};
            float bb[4] = {bv.x,bv.y,bv.z,bv.w};
#pragma unroll
            for (int i = 0; i < 8; i++)
#pragma unroll
                for (int j = 0; j < 4; j++) sacc[i][j] += aa[i] * bb[j];
        }
#pragma unroll
        for (int j = 0; j < 4; j++) {
            int s  = s0 + tx*4 + j;
            int cs = ck[tx*4 + j];
            float tmp[8];
#pragma unroll
            for (int i = 0; i < 8; i++) {
                int t = t0 + ty*8 + i;
                bool m = (s <= t) && (cs == cq[ty*8 + i]);
                tmp[i] = m ? sacc[i][j] : 0.0f;
            }
            *(float4*)&Ss[(tx*4+j)*PI + ty*8]     = make_float4(tmp[0],tmp[1],tmp[2],tmp[3]);
            *(float4*)&Ss[(tx*4+j)*PI + ty*8 + 4] = make_float4(tmp[4],tmp[5],tmp[6],tmp[7]);
        }
        __syncthreads();

#pragma unroll 8
        for (int s = 0; s < 64; s++) {
            float4 a0 = *(const float4*)&Ss[s*PI + ty*8];
            float4 a1 = *(const float4*)&Ss[s*PI + ty*8 + 4];
            float4 bv = *(const float4*)&vs[s*64 + tx*4];
            float aa[8] = {a0.x,a0.y,a0.z,a0.w,a1.x,a1.y,a1.z,a1.w};
            float bb[4] = {bv.x,bv.y,bv.z,bv.w};
#pragma unroll
            for (int i = 0; i < 8; i++)
#pragma unroll
                for (int j = 0; j < 4; j++) acc[i][j] += aa[i] * bb[j];
        }
        __syncthreads();
    }

    if (cum_t0 == 0) {
#pragma unroll
        for (int r = 0; r < 4; r++) {
            int idx = tid + r*256;
            int e = idx >> 4, c4 = (idx & 15) * 4;
            *(float4*)&ks[e*68 + c4] = *(const float4*)(state + (h*64 + e)*64 + c4);
        }
        __syncthreads();
        float sacc[8][4] = {};
#pragma unroll 8
        for (int e = 0; e < 64; e++) {
            float4 a0 = *(const float4*)&qs[e*PI + ty*8];
            float4 a1 = *(const float4*)&qs[e*PI + ty*8 + 4];
            float4 bv = *(const float4*)&ks[e*68 + tx*4];
            float aa[8] = {a0.x,a0.y,a0.z,a0.w,a1.x,a1.y,a1.z,a1.w};
            float bb[4] = {bv.x,bv.y,bv.z,bv.w};
#pragma unroll
            for (int i = 0; i < 8; i++)
#pragma unroll
                for (int j = 0; j < 4; j++) sacc[i][j] += aa[i] * bb[j];
        }
#pragma unroll
        for (int i = 0; i < 8; i++) {
            if (cq[ty*8 + i] == 0) {
#pragma unroll
                for (int j = 0; j < 4; j++) acc[i][j] += sacc[i][j];
            }
        }
    }

    float* og = g_ao + (h*T + t0)*DH;
#pragma unroll
    for (int i = 0; i < 8; i++) {
        *(float4*)&og[(ty*8+i)*DH + tx*4] = make_float4(acc[i][0],acc[i][1],acc[i][2],acc[i][3]);
    }
}

// ---------------- new_state: parallel partials + deterministic reduce ----------------
// grid (8, H): chunk-group c covers tokens [c*256, c*256+256) as 4 tiles of 64.
__global__ void newstate_partial_kernel() {
    __shared__ float kt[64][68];
    __shared__ float vt[64][64];
    int c = blockIdx.x;
    int h = blockIdx.y;
    int tid = threadIdx.x;
    int d = tid >> 2;
    int eg = (tid & 3) * 16;
    int cum_last = g_cum[T-1];
    float acc[16] = {};
    bool any = false;
    for (int ti = 0; ti < 4; ti++) {
        int t0 = c*256 + ti*64;
        if (g_cum[t0 + 63] < cum_last) continue;  // after_last is a suffix
        any = true;
#pragma unroll
        for (int r = 0; r < 4; r++) {
            int idx = tid + r*256;
            int tt = idx >> 4, c4 = (idx & 15) * 4;
            int t = t0 + tt;
            float m = (g_cum[t] == cum_last) ? 1.0f : 0.0f;
            float4 a = *(const float4*)(g_k + (h*T + t)*DH + c4);
            kt[tt][c4+0] = a.x*m; kt[tt][c4+1] = a.y*m;
            kt[tt][c4+2] = a.z*m; kt[tt][c4+3] = a.w*m;
            *(float4*)&vt[tt][c4] = *(const float4*)(g_v + (h*T + t)*DH + c4);
        }
        __syncthreads();
        for (int tt = 0; tt < 64; tt++) {
            float kv = kt[tt][d];
#pragma unroll
            for (int e4 = 0; e4 < 4; e4++) {
                float4 v4 = *(const float4*)&vt[tt][eg + e4*4];
                acc[e4*4+0] += kv * v4.x;
                acc[e4*4+1] += kv * v4.y;
                acc[e4*4+2] += kv * v4.z;
                acc[e4*4+3] += kv * v4.w;
            }
        }
        __syncthreads();
    }
    float* dst = &g_ns[c][h*4096 + d*64 + eg];
    if (any) {
#pragma unroll
        for (int e = 0; e < 16; e++) dst[e] = acc[e];
    } else {
#pragma unroll
        for (int e = 0; e < 16; e++) dst[e] = 0.0f;
    }
}

__global__ void newstate_reduce_kernel(const float* __restrict__ state,
                                       float* __restrict__ out) {
    int i = blockIdx.x * blockDim.x + threadIdx.x;  // 65536 total
    bool done_any = g_cum[T-1] > 0;
    float s = done_any ? 0.0f : state[i];
#pragma unroll
    for (int c = 0; c < 8; c++) s += g_ns[c][i];
    out[i] = s;
}

// ---------------- launch ----------------
static const int ATTN_SMEM = (64*PI + 64*68 + 64*64 + 64*PI) * 4 + (128 + 64) * 4;

extern "C" void kernel_launch(void* const* d_in, const int* in_sizes, int n_in,
                              void* d_out, int out_size) {
    const float* state  = (const float*)d_in[0];
    const float* x      = (const float*)d_in[1];
    const unsigned char* done = (const unsigned char*)d_in[2];
    const float* w_qkv  = (const float*)d_in[3];
    const float* b_qkv  = (const float*)d_in[4];
    const float* w_out  = (const float*)d_in[5];
    const float* b_out  = (const float*)d_in[6];

    float* out_state = (float*)d_out;            // H*DH*DH = 65536 elems
    float* out_x     = out_state + H*DH*DH;      // T*D elems

    cudaFuncSetAttribute(attn_kernel, cudaFuncAttributeMaxDynamicSharedMemorySize, ATTN_SMEM);

    cumsum_kernel<<<1, 256>>>(done);
    qkv_gemm_kernel<<<dim3(N3/64, T/128), 256>>>(x, w_qkv, b_qkv);
    attn_kernel<<<dim3(T/128, H), 256, ATTN_SMEM>>>(state);
    newstate_partial_kernel<<<dim3(8, H), 256>>>();
    newstate_reduce_kernel<<<64, 1024>>>(state, out_state);
    out_gemm_kernel<<<dim3(D/64, T/128), 256>>>(w_out, b_out, out_x);
}